// round 15
// baseline (speedup 1.0000x reference)
#include <cuda_runtime.h>
#include <cstdint>

#define BATCH 8
#define CH    512
#define TT    8192
#define KS    7
#define TPAD  (TT + 6)
#define WN    (CH * CH * KS)   // 1835008

// conv tiling: 128t x 32o CTA, 256 threads, 4 CTAs/SM
#define MT 128
#define NT 32
#define BK 128            // channels per stage
#define NSTG 28           // 4 ci-chunks * 7 taps
#define LD 144            // smem row stride: 16B-aligned, ldmatrix conflict-free
#define A_ROWS 134        // 128 + 6 halo (exact)
#define ABYTES (A_ROWS * LD)   // 19296
#define BBYTES (NT * LD)       // 4608
#define NBUF 4                 // B ring slots
#define SMEM_CONV (2 * ABYTES + NBUF * BBYTES)  // 57024 -> 4 CTAs/SM
#define APIECES (134 * 8)      // 1072 x 16B chunks per A tile
#define ASPREAD 268            // pieces per spread-group (4 groups: taps 3..6)

#define NSTATS 1024       // stats blocks (128 t-tiles of 64 * 8 batch)
#define NWSUM  448        // wsum partial blocks
#define NHALO  96         // halo-zero blocks
#define TOTALB (NSTATS + NWSUM + NHALO)   // 1568

// ---------------- device scratch (no runtime allocation) ----------------
__device__ __align__(16) int8_t g_xT[(size_t)BATCH * TPAD * CH]; // [b][t+3][c]
__device__ __align__(16) int8_t g_wq[(size_t)KS * CH * CH];      // [tap][o][i]
__device__ float        g_rms[BATCH * TT];
__device__ float        g_pmax[NSTATS];
__device__ double       g_psum[NWSUM];
__device__ int          g_cnt = 0;   // last-block counter (reset by combiner)
__device__ float        g_qmul;   // 127 / act_scale
__device__ float        g_winv;   // 1 / w_scale
__device__ float        g_comb;   // act_scale/127 * w_scale

// ---------------- ptx helpers (sm_80-level; harness target is sm_103) -------
__device__ __forceinline__ uint32_t smem_u32(const void* p) {
    uint32_t a;
    asm("{ .reg .u64 t; cvta.to.shared.u64 t, %1; cvt.u32.u64 %0, t; }"
        : "=r"(a) : "l"(p));
    return a;
}
#define CP_ASYNC16(dst, src) \
    asm volatile("cp.async.cg.shared.global [%0], [%1], 16;" \
                 :: "r"(dst), "l"(src) : "memory")
#define CP_COMMIT() asm volatile("cp.async.commit_group;" ::: "memory")
#define CP_WAIT2()  asm volatile("cp.async.wait_group 2;" ::: "memory")

__device__ __forceinline__ void ldsm_x4(uint32_t* r, uint32_t addr) {
    asm volatile(
        "ldmatrix.sync.aligned.m8n8.x4.shared.b16 {%0,%1,%2,%3}, [%4];"
        : "=r"(r[0]), "=r"(r[1]), "=r"(r[2]), "=r"(r[3]) : "r"(addr));
}
__device__ __forceinline__ void mma_s8(int* c, const uint32_t* a,
                                       uint32_t b0, uint32_t b1) {
    asm volatile(
        "mma.sync.aligned.m16n8k32.row.col.s32.s8.s8.s32 "
        "{%0,%1,%2,%3}, {%4,%5,%6,%7}, {%8,%9}, {%0,%1,%2,%3};"
        : "+r"(c[0]), "+r"(c[1]), "+r"(c[2]), "+r"(c[3])
        : "r"(a[0]), "r"(a[1]), "r"(a[2]), "r"(a[3]), "r"(b0), "r"(b1));
}

// ---------------- L1: k_pre — stats + wsum partials + halo zero + combine ---
__global__ void k_pre(const float* __restrict__ x,
                      const float* __restrict__ gamma,
                      const float* __restrict__ w) {
    int bid = blockIdx.x;
    int tid = threadIdx.x;
    if (bid < NSTATS) {
        __shared__ float sg[CH];
        __shared__ float sss[16][64];
        __shared__ float smx[16][64];
        __shared__ float sred[2];
        sg[tid] = gamma[tid];
        sg[tid + 256] = gamma[tid + 256];
        __syncthreads();
        int b  = bid >> 7;
        int t0 = (bid & 127) << 6;    // 64 t per block
        int tq = tid & 15;            // t-quad index: t = t0 + tq*4 + j
        int cg = tid >> 4;            // 0..15
        const float4* xp = reinterpret_cast<const float4*>(
            x + (size_t)b * CH * TT + t0);
        float ss0 = 0.f, ss1 = 0.f, ss2 = 0.f, ss3 = 0.f;
        float mx0 = 0.f, mx1 = 0.f, mx2 = 0.f, mx3 = 0.f;
        for (int c = cg; c < CH; c += 16) {
            float4 v = xp[(size_t)c * (TT / 4) + tq];
            float g = sg[c];
            ss0 += v.x * v.x; mx0 = fmaxf(mx0, fabsf(v.x * g));
            ss1 += v.y * v.y; mx1 = fmaxf(mx1, fabsf(v.y * g));
            ss2 += v.z * v.z; mx2 = fmaxf(mx2, fabsf(v.z * g));
            ss3 += v.w * v.w; mx3 = fmaxf(mx3, fabsf(v.w * g));
        }
        sss[cg][tq * 4 + 0] = ss0; smx[cg][tq * 4 + 0] = mx0;
        sss[cg][tq * 4 + 1] = ss1; smx[cg][tq * 4 + 1] = mx1;
        sss[cg][tq * 4 + 2] = ss2; smx[cg][tq * 4 + 2] = mx2;
        sss[cg][tq * 4 + 3] = ss3; smx[cg][tq * 4 + 3] = mx3;
        __syncthreads();
        if (tid < 64) {
            float S = 0.f, M = 0.f;
#pragma unroll
            for (int g = 0; g < 16; g++) {
                S += sss[g][tid];
                M = fmaxf(M, smx[g][tid]);
            }
            float rms = 1.0f / sqrtf(S * (1.0f / (float)CH) + 1e-6f);
            g_rms[b * TT + t0 + tid] = rms;
            float cand = M * rms;
#pragma unroll
            for (int o = 16; o; o >>= 1)
                cand = fmaxf(cand, __shfl_xor_sync(0xffffffffu, cand, o));
            if ((tid & 31) == 0) sred[tid >> 5] = cand;
        }
        __syncthreads();
        if (tid == 0) g_pmax[bid] = fmaxf(sred[0], sred[1]);
    } else if (bid < NSTATS + NWSUM) {
        int j = bid - NSTATS;
        double s = 0.0;
        for (int i = j * 256 + tid; i < WN; i += NWSUM * 256)
            s += (double)fabsf(w[i]);
#pragma unroll
        for (int o = 16; o; o >>= 1) s += __shfl_xor_sync(0xffffffffu, s, o);
        __shared__ double sdp[8];
        if ((tid & 31) == 0) sdp[tid >> 5] = s;
        __syncthreads();
        if (tid == 0) {
            double t = 0.0;
#pragma unroll
            for (int g = 0; g < 8; g++) t += sdp[g];
            g_psum[j] = t;
        }
    } else {
        int idx = (bid - NSTATS - NWSUM) * 256 + tid;   // [0, 24576)
        int b = idx / (6 * CH);
        int r = (idx / CH) % 6;
        int c = idx % CH;
        int row = (r < 3) ? r : (TT + r);
        g_xT[((size_t)b * TPAD + row) * CH + c] = 0;
    }

    // ---- last-block combine: partials -> scalars (deterministic) ----
    __shared__ int slast;
    __syncthreads();
    if (tid == 0) {
        __threadfence();                       // publish g_pmax / g_psum
        int c = atomicAdd(&g_cnt, 1);
        slast = (c == TOTALB - 1) ? 1 : 0;
    }
    __syncthreads();
    if (slast) {
        __shared__ double sd[256];
        __shared__ float  sf[256];
        double s = 0.0;
        for (int i = tid; i < NWSUM; i += 256) s += g_psum[i];
        float m = 0.f;
        for (int i = tid; i < NSTATS; i += 256) m = fmaxf(m, g_pmax[i]);
        sd[tid] = s;
        sf[tid] = m;
        __syncthreads();
        for (int o = 128; o; o >>= 1) {
            if (tid < o) {
                sd[tid] += sd[tid + o];
                sf[tid] = fmaxf(sf[tid], sf[tid + o]);
            }
            __syncthreads();
        }
        if (tid == 0) {
            float act = fmaxf(sf[0], 1e-5f);
            float ws  = fmaxf((float)(sd[0] / (double)WN), 1e-4f);
            g_qmul = 127.0f / act;
            g_winv = 1.0f / ws;
            g_comb = act * (1.0f / 127.0f) * ws;
            g_cnt  = 0;                        // replay-safe reset
        }
    }
}

// ---------------- L2: k_mid — act quant/transpose + fused weight quant ------
// 8192 blocks: quant tile (128c x 32t) + <=1 weight element per thread
__global__ void k_mid(const float* __restrict__ x,
                      const float* __restrict__ gamma,
                      const float* __restrict__ w) {
    int bid = blockIdx.x;
    int tid = threadIdx.x;
    {
        __shared__ int8_t s[128][33];   // [c][t], conflict-free byte gather
        __shared__ float  sg[128];
        int bx = bid & 255;             // 256 t-tiles of 32
        int by = (bid >> 8) & 3;        // 4 c-tiles of 128
        int b  = bid >> 10;
        int t0 = bx * 32;
        int c0 = by * 128;
        int tq = tid & 7;               // t-quad: t = t0 + tq*4 + j
        int cg = tid >> 3;              // 0..31, c stride 32
        if (tid < 128) sg[tid] = gamma[c0 + tid] * g_qmul;
        float r0 = g_rms[b * TT + t0 + tq * 4 + 0];
        float r1 = g_rms[b * TT + t0 + tq * 4 + 1];
        float r2 = g_rms[b * TT + t0 + tq * 4 + 2];
        float r3 = g_rms[b * TT + t0 + tq * 4 + 3];

        // fused ternary weight quant: one strided element per thread
        int widx = bid * 256 + tid;
        if (widx < WN) {
            float q = rintf(fminf(fmaxf(w[widx] * g_winv, -1.0f), 1.0f));
            int tap = widx % KS;
            int i   = (widx / KS) & (CH - 1);
            int o   = widx / (KS * CH);
            g_wq[(size_t)tap * (CH * CH) + (size_t)o * CH + i] = (int8_t)q;
        }

        __syncthreads();
        const float4* xb = reinterpret_cast<const float4*>(
            x + (size_t)b * CH * TT + t0);
#pragma unroll
        for (int cc = cg; cc < 128; cc += 32) {
            float4 v = xb[(size_t)(c0 + cc) * (TT / 4) + tq];
            float gq = sg[cc];
            s[cc][tq * 4 + 0] =
                (int8_t)rintf(fminf(fmaxf(v.x * r0 * gq, -128.f), 127.f));
            s[cc][tq * 4 + 1] =
                (int8_t)rintf(fminf(fmaxf(v.y * r1 * gq, -128.f), 127.f));
            s[cc][tq * 4 + 2] =
                (int8_t)rintf(fminf(fmaxf(v.z * r2 * gq, -128.f), 127.f));
            s[cc][tq * 4 + 3] =
                (int8_t)rintf(fminf(fmaxf(v.w * r3 * gq, -128.f), 127.f));
        }
        __syncthreads();
        // transpose store: warp covers one t-row of 128 c = 128B coalesced
        int co4  = (tid & 31) * 4;
        int wrow = tid >> 5;            // 0..7
#pragma unroll
        for (int k = 0; k < 4; k++) {
            int tw = wrow + k * 8;
            uchar4 v;
            v.x = (unsigned char)s[co4 + 0][tw];
            v.y = (unsigned char)s[co4 + 1][tw];
            v.z = (unsigned char)s[co4 + 2][tw];
            v.w = (unsigned char)s[co4 + 3][tw];
            *reinterpret_cast<uchar4*>(
                g_xT + ((size_t)b * TPAD + t0 + tw + 3) * CH + c0 + co4) = v;
        }
    }
}

// ---------------- L3: pipelined IMMA conv-GEMM, 4 CTAs/SM --------------------
// (unchanged from R12/R13 winner: 97.1% tensor-pipe busy)
struct ConvPtrs {
    const int8_t* xb;
    const int8_t* wb;
    uint32_t As_u[2];
    uint32_t Bs_u[NBUF];
};

__device__ __forceinline__ void load_a_piece(uint32_t ad, const int8_t* src, int p) {
    int row = p >> 3, seg = p & 7;
    CP_ASYNC16(ad + row * LD + seg * 16, src + (size_t)row * CH + seg * 16);
}

__device__ __forceinline__ void issue_stage(int j, const ConvPtrs& P, int tid) {
    int tap = j % 7;
    int n   = j / 7;
    {   // B tile: 32 rows x 128B = 256 chunks -> 1 per thread
        uint32_t bd = P.Bs_u[j & (NBUF - 1)];
        const int8_t* src = P.wb + (size_t)tap * (CH * CH) + (size_t)n * BK;
        int row = tid >> 3, seg = tid & 7;
        CP_ASYNC16(bd + row * LD + seg * 16,
                   src + (size_t)row * CH + seg * 16);
    }
    if (tap >= 3 && n + 1 < 4) {
        uint32_t ad = P.As_u[(n + 1) & 1];
        const int8_t* src = P.xb + (size_t)(n + 1) * BK;
        int p0 = (tap - 3) * ASPREAD;
        int p  = p0 + tid;
        if (p < p0 + ASPREAD && p < APIECES) load_a_piece(ad, src, p);
        p += 256;
        if (p < p0 + ASPREAD && p < APIECES) load_a_piece(ad, src, p);
    }
}

__global__ void __launch_bounds__(256, 4) k_conv(float* __restrict__ out) {
    extern __shared__ __align__(128) char sm[];

    int b  = blockIdx.z;
    int t0 = blockIdx.x * MT;
    int o0 = blockIdx.y * NT;
    int tid   = threadIdx.x;
    int warp  = tid >> 5;
    int lane  = tid & 31;
    int warpM = warp >> 1;   // 0..3 : 32 t rows
    int warpN = warp & 1;    // 0..1 : 16 o cols

    ConvPtrs P;
    P.xb = g_xT + ((size_t)b * TPAD + t0) * CH;
    P.wb = g_wq + (size_t)o0 * CH;
    uint32_t base = smem_u32(sm);
    P.As_u[0] = base;
    P.As_u[1] = base + ABYTES;
#pragma unroll
    for (int s = 0; s < NBUF; s++) P.Bs_u[s] = base + 2 * ABYTES + s * BBYTES;

    int acc[2][2][4];
#pragma unroll
    for (int i = 0; i < 2; i++)
#pragma unroll
        for (int j = 0; j < 2; j++)
#pragma unroll
            for (int q = 0; q < 4; q++) acc[i][j][q] = 0;

    uint32_t l_row = (((lane >> 3) & 1) << 3) + (lane & 7);
    uint32_t l_col = ((lane >> 4) & 1) << 4;

    // prologue: group0 = A(chunk0)+A(chunk1)+B(stage0); group1 = B(stage1)
    {
        for (int p = tid; p < APIECES; p += 256) {
            load_a_piece(P.As_u[0], P.xb, p);
            load_a_piece(P.As_u[1], P.xb + BK, p);
        }
        int row = tid >> 3, seg = tid & 7;
        const int8_t* src = P.wb;   // stage 0: tap 0, ci 0
        CP_ASYNC16(P.Bs_u[0] + row * LD + seg * 16,
                   src + (size_t)row * CH + seg * 16);
        CP_COMMIT();
        src = P.wb + (size_t)1 * (CH * CH);   // stage 1: tap 1, ci 0
        CP_ASYNC16(P.Bs_u[1] + row * LD + seg * 16,
                   src + (size_t)row * CH + seg * 16);
        CP_COMMIT();
    }

#pragma unroll 1
    for (int it = 0; it < NSTG; it++) {
        if (it + 2 < NSTG) issue_stage(it + 2, P, tid);
        CP_COMMIT();
        CP_WAIT2();          // stage it data complete
        __syncthreads();     // visibility + slot-reuse fence

        int tap = it % 7;
        uint32_t a_base = P.As_u[(it / 7) & 1]
                        + (warpM * 32 + tap + l_row) * LD + l_col;
        uint32_t b_base = P.Bs_u[it & (NBUF - 1)]
                        + (warpN * 16 + l_row) * LD + l_col;

#pragma unroll
        for (int kk = 0; kk < 4; kk++) {
            uint32_t br[4];
            ldsm_x4(br, b_base + kk * 32);
#pragma unroll
            for (int mi = 0; mi < 2; mi++) {
                uint32_t ar[4];
                ldsm_x4(ar, a_base + mi * 16 * LD + kk * 32);
#pragma unroll
                for (int ni = 0; ni < 2; ni++)
                    mma_s8(acc[mi][ni], ar, br[ni], br[ni + 2]);
            }
        }
    }

    // ---- epilogue: per-warp 16x20 float staging, transpose to out[o][t] ----
    __syncthreads();
    float comb = g_comb;
    float* ep = reinterpret_cast<float*>(sm) + warp * (16 * 20);
    int r  = lane >> 2;
    int c2 = (lane & 3) * 2;
#pragma unroll 1
    for (int mi = 0; mi < 2; mi++) {
#pragma unroll
        for (int ni = 0; ni < 2; ni++) {
            ep[r * 20 + ni * 8 + c2]           = (float)acc[mi][ni][0] * comb;
            ep[r * 20 + ni * 8 + c2 + 1]       = (float)acc[mi][ni][1] * comb;
            ep[(r + 8) * 20 + ni * 8 + c2]     = (float)acc[mi][ni][2] * comb;
            ep[(r + 8) * 20 + ni * 8 + c2 + 1] = (float)acc[mi][ni][3] * comb;
        }
        __syncwarp();
        int tb = t0 + warpM * 32 + mi * 16;
        int ol = lane & 15;
        int tq = lane >> 4;          // 0..1
        float* op = out + ((size_t)b * CH + o0 + warpN * 16 + ol) * (size_t)TT + tb;
#pragma unroll
        for (int q = 0; q < 2; q++) {
            int t4 = (tq + q * 2) * 4;
            float4 v;
            v.x = ep[(t4 + 0) * 20 + ol];
            v.y = ep[(t4 + 1) * 20 + ol];
            v.z = ep[(t4 + 2) * 20 + ol];
            v.w = ep[(t4 + 3) * 20 + ol];
            *reinterpret_cast<float4*>(op + t4) = v;
        }
        __syncwarp();
    }
}

// ---------------- launch (3 launches) ----------------
extern "C" void kernel_launch(void* const* d_in, const int* in_sizes, int n_in,
                              void* d_out, int out_size) {
    const float* x     = (const float*)d_in[0];   // (8, 512, 8192)
    const float* w     = (const float*)d_in[1];   // (512, 512, 7)
    const float* gamma = (const float*)d_in[2];   // (512,)
    float* out = (float*)d_out;                   // (8, 512, 8192)

    cudaFuncSetAttribute(k_conv, cudaFuncAttributeMaxDynamicSharedMemorySize,
                         SMEM_CONV);

    k_pre<<<TOTALB, 256>>>(x, gamma, w);
    k_mid<<<8192, 256>>>(x, gamma, w);
    k_conv<<<dim3(TT / MT, CH / NT, BATCH), 256, SMEM_CONV>>>(out);
}

// round 16
// speedup vs baseline: 1.0026x; 1.0026x over previous
#include <cuda_runtime.h>
#include <cstdint>

#define BATCH 8
#define CH    512
#define TT    8192
#define KS    7
#define TPAD  (TT + 6)
#define WN    (CH * CH * KS)   // 1835008

// conv tiling: 128t x 32o CTA, 256 threads, 4 CTAs/SM
#define MT 128
#define NT 32
#define BK 128            // channels per stage
#define NSTG 28           // 4 ci-chunks * 7 taps
#define LD 144            // smem row stride: 16B-aligned, ldmatrix conflict-free
#define A_ROWS 134        // 128 + 6 halo (exact)
#define ABYTES (A_ROWS * LD)   // 19296
#define BBYTES (NT * LD)       // 4608
#define NBUF 4                 // B ring slots
#define SMEM_CONV (2 * ABYTES + NBUF * BBYTES)  // 57024 -> 4 CTAs/SM
#define APIECES (134 * 8)      // 1072 x 16B chunks per A tile
#define ASPREAD 268            // pieces per spread-group (4 groups: taps 3..6)

#define NSTATS 512        // stats blocks (64 t-tiles of 128 * 8 batch)
#define NWSUM  448        // wsum partial blocks
#define NHALO  96         // halo-zero blocks
#define TOTALB (NSTATS + NWSUM + NHALO)   // 1056

// ---------------- device scratch (no runtime allocation) ----------------
__device__ __align__(16) int8_t g_xT[(size_t)BATCH * TPAD * CH]; // [b][t+3][c]
__device__ __align__(16) int8_t g_wq[(size_t)KS * CH * CH];      // [tap][o][i]
__device__ float        g_rms[BATCH * TT];
__device__ float        g_pmax[NSTATS];
__device__ double       g_psum[NWSUM];
__device__ int          g_cnt = 0;   // last-block counter (reset by combiner)
__device__ float        g_qmul;   // 127 / act_scale
__device__ float        g_winv;   // 1 / w_scale
__device__ float        g_comb;   // act_scale/127 * w_scale

// ---------------- ptx helpers (sm_80-level; harness target is sm_103) -------
__device__ __forceinline__ uint32_t smem_u32(const void* p) {
    uint32_t a;
    asm("{ .reg .u64 t; cvta.to.shared.u64 t, %1; cvt.u32.u64 %0, t; }"
        : "=r"(a) : "l"(p));
    return a;
}
#define CP_ASYNC16(dst, src) \
    asm volatile("cp.async.cg.shared.global [%0], [%1], 16;" \
                 :: "r"(dst), "l"(src) : "memory")
#define CP_COMMIT() asm volatile("cp.async.commit_group;" ::: "memory")
#define CP_WAIT2()  asm volatile("cp.async.wait_group 2;" ::: "memory")

__device__ __forceinline__ void ldsm_x4(uint32_t* r, uint32_t addr) {
    asm volatile(
        "ldmatrix.sync.aligned.m8n8.x4.shared.b16 {%0,%1,%2,%3}, [%4];"
        : "=r"(r[0]), "=r"(r[1]), "=r"(r[2]), "=r"(r[3]) : "r"(addr));
}
__device__ __forceinline__ void mma_s8(int* c, const uint32_t* a,
                                       uint32_t b0, uint32_t b1) {
    asm volatile(
        "mma.sync.aligned.m16n8k32.row.col.s32.s8.s8.s32 "
        "{%0,%1,%2,%3}, {%4,%5,%6,%7}, {%8,%9}, {%0,%1,%2,%3};"
        : "+r"(c[0]), "+r"(c[1]), "+r"(c[2]), "+r"(c[3])
        : "r"(a[0]), "r"(a[1]), "r"(a[2]), "r"(a[3]), "r"(b0), "r"(b1));
}

// ---------------- L1: k_pre — stats + wsum partials + halo zero + combine ---
// stats: R14 shape (512 blocks x 128 t) — measured 33.7us @ DRAM 54.7%
__global__ void k_pre(const float* __restrict__ x,
                      const float* __restrict__ gamma,
                      const float* __restrict__ w) {
    int bid = blockIdx.x;
    int tid = threadIdx.x;
    if (bid < NSTATS) {
        __shared__ float sg[CH];
        __shared__ float sss[8][128];
        __shared__ float smx[8][128];
        sg[tid] = gamma[tid];
        sg[tid + 256] = gamma[tid + 256];
        __syncthreads();
        int b  = bid >> 6;
        int t0 = (bid & 63) << 7;     // 128 t per block
        int tq = tid & 31;            // t-quad index: t = t0 + tq*4 + j
        int cg = tid >> 5;            // 0..7
        const float4* xp = reinterpret_cast<const float4*>(
            x + (size_t)b * CH * TT + t0);
        float ss0 = 0.f, ss1 = 0.f, ss2 = 0.f, ss3 = 0.f;
        float mx0 = 0.f, mx1 = 0.f, mx2 = 0.f, mx3 = 0.f;
        for (int c = cg; c < CH; c += 8) {
            float4 v = xp[(size_t)c * (TT / 4) + tq];
            float g = sg[c];
            ss0 += v.x * v.x; mx0 = fmaxf(mx0, fabsf(v.x * g));
            ss1 += v.y * v.y; mx1 = fmaxf(mx1, fabsf(v.y * g));
            ss2 += v.z * v.z; mx2 = fmaxf(mx2, fabsf(v.z * g));
            ss3 += v.w * v.w; mx3 = fmaxf(mx3, fabsf(v.w * g));
        }
        sss[cg][0 * 32 + tq] = ss0; smx[cg][0 * 32 + tq] = mx0;
        sss[cg][1 * 32 + tq] = ss1; smx[cg][1 * 32 + tq] = mx1;
        sss[cg][2 * 32 + tq] = ss2; smx[cg][2 * 32 + tq] = mx2;
        sss[cg][3 * 32 + tq] = ss3; smx[cg][3 * 32 + tq] = mx3;
        __syncthreads();
        if (cg == 0) {
            float cand = 0.f;
#pragma unroll
            for (int j = 0; j < 4; j++) {
                float S = 0.f, M = 0.f;
#pragma unroll
                for (int g = 0; g < 8; g++) {
                    S += sss[g][j * 32 + tq];
                    M = fmaxf(M, smx[g][j * 32 + tq]);
                }
                float rms = 1.0f / sqrtf(S * (1.0f / (float)CH) + 1e-6f);
                g_rms[b * TT + t0 + tq * 4 + j] = rms;
                cand = fmaxf(cand, M * rms);
            }
#pragma unroll
            for (int o = 16; o; o >>= 1)
                cand = fmaxf(cand, __shfl_xor_sync(0xffffffffu, cand, o));
            if (tq == 0) g_pmax[bid] = cand;
        }
    } else if (bid < NSTATS + NWSUM) {
        int j = bid - NSTATS;
        double s = 0.0;
        for (int i = j * 256 + tid; i < WN; i += NWSUM * 256)
            s += (double)fabsf(w[i]);
#pragma unroll
        for (int o = 16; o; o >>= 1) s += __shfl_xor_sync(0xffffffffu, s, o);
        __shared__ double sdp[8];
        if ((tid & 31) == 0) sdp[tid >> 5] = s;
        __syncthreads();
        if (tid == 0) {
            double t = 0.0;
#pragma unroll
            for (int g = 0; g < 8; g++) t += sdp[g];
            g_psum[j] = t;
        }
    } else {
        int idx = (bid - NSTATS - NWSUM) * 256 + tid;   // [0, 24576)
        int b = idx / (6 * CH);
        int r = (idx / CH) % 6;
        int c = idx % CH;
        int row = (r < 3) ? r : (TT + r);
        g_xT[((size_t)b * TPAD + row) * CH + c] = 0;
    }

    // ---- last-block combine: partials -> scalars (deterministic) ----
    __shared__ int slast;
    __syncthreads();
    if (tid == 0) {
        __threadfence();                       // publish g_pmax / g_psum
        int c = atomicAdd(&g_cnt, 1);
        slast = (c == TOTALB - 1) ? 1 : 0;
    }
    __syncthreads();
    if (slast) {
        __shared__ double sd[256];
        __shared__ float  sf[256];
        double s = 0.0;
        for (int i = tid; i < NWSUM; i += 256) s += g_psum[i];
        float m = 0.f;
        for (int i = tid; i < NSTATS; i += 256) m = fmaxf(m, g_pmax[i]);
        sd[tid] = s;
        sf[tid] = m;
        __syncthreads();
        for (int o = 128; o; o >>= 1) {
            if (tid < o) {
                sd[tid] += sd[tid + o];
                sf[tid] = fmaxf(sf[tid], sf[tid + o]);
            }
            __syncthreads();
        }
        if (tid == 0) {
            float act = fmaxf(sf[0], 1e-5f);
            float ws  = fmaxf((float)(sd[0] / (double)WN), 1e-4f);
            g_qmul = 127.0f / act;
            g_winv = 1.0f / ws;
            g_comb = act * (1.0f / 127.0f) * ws;
            g_cnt  = 0;                        // replay-safe reset
        }
    }
}

// ---------------- L2: k_mid — act quant/transpose + fused weight quant ------
// 8192 blocks: quant tile (128c x 32t) + <=1 weight element per thread
__global__ void k_mid(const float* __restrict__ x,
                      const float* __restrict__ gamma,
                      const float* __restrict__ w) {
    int bid = blockIdx.x;
    int tid = threadIdx.x;
    {
        __shared__ int8_t s[128][33];   // [c][t], conflict-free byte gather
        __shared__ float  sg[128];
        int bx = bid & 255;             // 256 t-tiles of 32
        int by = (bid >> 8) & 3;        // 4 c-tiles of 128
        int b  = bid >> 10;
        int t0 = bx * 32;
        int c0 = by * 128;
        int tq = tid & 7;               // t-quad: t = t0 + tq*4 + j
        int cg = tid >> 3;              // 0..31, c stride 32
        if (tid < 128) sg[tid] = gamma[c0 + tid] * g_qmul;
        float r0 = g_rms[b * TT + t0 + tq * 4 + 0];
        float r1 = g_rms[b * TT + t0 + tq * 4 + 1];
        float r2 = g_rms[b * TT + t0 + tq * 4 + 2];
        float r3 = g_rms[b * TT + t0 + tq * 4 + 3];

        // fused ternary weight quant: one strided element per thread
        int widx = bid * 256 + tid;
        if (widx < WN) {
            float q = rintf(fminf(fmaxf(w[widx] * g_winv, -1.0f), 1.0f));
            int tap = widx % KS;
            int i   = (widx / KS) & (CH - 1);
            int o   = widx / (KS * CH);
            g_wq[(size_t)tap * (CH * CH) + (size_t)o * CH + i] = (int8_t)q;
        }

        __syncthreads();
        const float4* xb = reinterpret_cast<const float4*>(
            x + (size_t)b * CH * TT + t0);
#pragma unroll
        for (int cc = cg; cc < 128; cc += 32) {
            float4 v = xb[(size_t)(c0 + cc) * (TT / 4) + tq];
            float gq = sg[cc];
            s[cc][tq * 4 + 0] =
                (int8_t)rintf(fminf(fmaxf(v.x * r0 * gq, -128.f), 127.f));
            s[cc][tq * 4 + 1] =
                (int8_t)rintf(fminf(fmaxf(v.y * r1 * gq, -128.f), 127.f));
            s[cc][tq * 4 + 2] =
                (int8_t)rintf(fminf(fmaxf(v.z * r2 * gq, -128.f), 127.f));
            s[cc][tq * 4 + 3] =
                (int8_t)rintf(fminf(fmaxf(v.w * r3 * gq, -128.f), 127.f));
        }
        __syncthreads();
        // transpose store: warp covers one t-row of 128 c = 128B coalesced
        int co4  = (tid & 31) * 4;
        int wrow = tid >> 5;            // 0..7
#pragma unroll
        for (int k = 0; k < 4; k++) {
            int tw = wrow + k * 8;
            uchar4 v;
            v.x = (unsigned char)s[co4 + 0][tw];
            v.y = (unsigned char)s[co4 + 1][tw];
            v.z = (unsigned char)s[co4 + 2][tw];
            v.w = (unsigned char)s[co4 + 3][tw];
            *reinterpret_cast<uchar4*>(
                g_xT + ((size_t)b * TPAD + t0 + tw + 3) * CH + c0 + co4) = v;
        }
    }
}

// ---------------- L3: pipelined IMMA conv-GEMM, 4 CTAs/SM --------------------
// (unchanged from R12-R15 winner: 97.1% tensor-pipe busy)
struct ConvPtrs {
    const int8_t* xb;
    const int8_t* wb;
    uint32_t As_u[2];
    uint32_t Bs_u[NBUF];
};

__device__ __forceinline__ void load_a_piece(uint32_t ad, const int8_t* src, int p) {
    int row = p >> 3, seg = p & 7;
    CP_ASYNC16(ad + row * LD + seg * 16, src + (size_t)row * CH + seg * 16);
}

__device__ __forceinline__ void issue_stage(int j, const ConvPtrs& P, int tid) {
    int tap = j % 7;
    int n   = j / 7;
    {   // B tile: 32 rows x 128B = 256 chunks -> 1 per thread
        uint32_t bd = P.Bs_u[j & (NBUF - 1)];
        const int8_t* src = P.wb + (size_t)tap * (CH * CH) + (size_t)n * BK;
        int row = tid >> 3, seg = tid & 7;
        CP_ASYNC16(bd + row * LD + seg * 16,
                   src + (size_t)row * CH + seg * 16);
    }
    if (tap >= 3 && n + 1 < 4) {
        uint32_t ad = P.As_u[(n + 1) & 1];
        const int8_t* src = P.xb + (size_t)(n + 1) * BK;
        int p0 = (tap - 3) * ASPREAD;
        int p  = p0 + tid;
        if (p < p0 + ASPREAD && p < APIECES) load_a_piece(ad, src, p);
        p += 256;
        if (p < p0 + ASPREAD && p < APIECES) load_a_piece(ad, src, p);
    }
}

__global__ void __launch_bounds__(256, 4) k_conv(float* __restrict__ out) {
    extern __shared__ __align__(128) char sm[];

    int b  = blockIdx.z;
    int t0 = blockIdx.x * MT;
    int o0 = blockIdx.y * NT;
    int tid   = threadIdx.x;
    int warp  = tid >> 5;
    int lane  = tid & 31;
    int warpM = warp >> 1;   // 0..3 : 32 t rows
    int warpN = warp & 1;    // 0..1 : 16 o cols

    ConvPtrs P;
    P.xb = g_xT + ((size_t)b * TPAD + t0) * CH;
    P.wb = g_wq + (size_t)o0 * CH;
    uint32_t base = smem_u32(sm);
    P.As_u[0] = base;
    P.As_u[1] = base + ABYTES;
#pragma unroll
    for (int s = 0; s < NBUF; s++) P.Bs_u[s] = base + 2 * ABYTES + s * BBYTES;

    int acc[2][2][4];
#pragma unroll
    for (int i = 0; i < 2; i++)
#pragma unroll
        for (int j = 0; j < 2; j++)
#pragma unroll
            for (int q = 0; q < 4; q++) acc[i][j][q] = 0;

    uint32_t l_row = (((lane >> 3) & 1) << 3) + (lane & 7);
    uint32_t l_col = ((lane >> 4) & 1) << 4;

    // prologue: group0 = A(chunk0)+A(chunk1)+B(stage0); group1 = B(stage1)
    {
        for (int p = tid; p < APIECES; p += 256) {
            load_a_piece(P.As_u[0], P.xb, p);
            load_a_piece(P.As_u[1], P.xb + BK, p);
        }
        int row = tid >> 3, seg = tid & 7;
        const int8_t* src = P.wb;   // stage 0: tap 0, ci 0
        CP_ASYNC16(P.Bs_u[0] + row * LD + seg * 16,
                   src + (size_t)row * CH + seg * 16);
        CP_COMMIT();
        src = P.wb + (size_t)1 * (CH * CH);   // stage 1: tap 1, ci 0
        CP_ASYNC16(P.Bs_u[1] + row * LD + seg * 16,
                   src + (size_t)row * CH + seg * 16);
        CP_COMMIT();
    }

#pragma unroll 1
    for (int it = 0; it < NSTG; it++) {
        if (it + 2 < NSTG) issue_stage(it + 2, P, tid);
        CP_COMMIT();
        CP_WAIT2();          // stage it data complete
        __syncthreads();     // visibility + slot-reuse fence

        int tap = it % 7;
        uint32_t a_base = P.As_u[(it / 7) & 1]
                        + (warpM * 32 + tap + l_row) * LD + l_col;
        uint32_t b_base = P.Bs_u[it & (NBUF - 1)]
                        + (warpN * 16 + l_row) * LD + l_col;

#pragma unroll
        for (int kk = 0; kk < 4; kk++) {
            uint32_t br[4];
            ldsm_x4(br, b_base + kk * 32);
#pragma unroll
            for (int mi = 0; mi < 2; mi++) {
                uint32_t ar[4];
                ldsm_x4(ar, a_base + mi * 16 * LD + kk * 32);
#pragma unroll
                for (int ni = 0; ni < 2; ni++)
                    mma_s8(acc[mi][ni], ar, br[ni], br[ni + 2]);
            }
        }
    }

    // ---- epilogue: per-warp 16x20 float staging, transpose to out[o][t] ----
    __syncthreads();
    float comb = g_comb;
    float* ep = reinterpret_cast<float*>(sm) + warp * (16 * 20);
    int r  = lane >> 2;
    int c2 = (lane & 3) * 2;
#pragma unroll 1
    for (int mi = 0; mi < 2; mi++) {
#pragma unroll
        for (int ni = 0; ni < 2; ni++) {
            ep[r * 20 + ni * 8 + c2]           = (float)acc[mi][ni][0] * comb;
            ep[r * 20 + ni * 8 + c2 + 1]       = (float)acc[mi][ni][1] * comb;
            ep[(r + 8) * 20 + ni * 8 + c2]     = (float)acc[mi][ni][2] * comb;
            ep[(r + 8) * 20 + ni * 8 + c2 + 1] = (float)acc[mi][ni][3] * comb;
        }
        __syncwarp();
        int tb = t0 + warpM * 32 + mi * 16;
        int ol = lane & 15;
        int tq = lane >> 4;          // 0..1
        float* op = out + ((size_t)b * CH + o0 + warpN * 16 + ol) * (size_t)TT + tb;
#pragma unroll
        for (int q = 0; q < 2; q++) {
            int t4 = (tq + q * 2) * 4;
            float4 v;
            v.x = ep[(t4 + 0) * 20 + ol];
            v.y = ep[(t4 + 1) * 20 + ol];
            v.z = ep[(t4 + 2) * 20 + ol];
            v.w = ep[(t4 + 3) * 20 + ol];
            *reinterpret_cast<float4*>(op + t4) = v;
        }
        __syncwarp();
    }
}

// ---------------- launch (3 launches) ----------------
extern "C" void kernel_launch(void* const* d_in, const int* in_sizes, int n_in,
                              void* d_out, int out_size) {
    const float* x     = (const float*)d_in[0];   // (8, 512, 8192)
    const float* w     = (const float*)d_in[1];   // (512, 512, 7)
    const float* gamma = (const float*)d_in[2];   // (512,)
    float* out = (float*)d_out;                   // (8, 512, 8192)

    cudaFuncSetAttribute(k_conv, cudaFuncAttributeMaxDynamicSharedMemorySize,
                         SMEM_CONV);

    k_pre<<<TOTALB, 256>>>(x, gamma, w);
    k_mid<<<8192, 256>>>(x, gamma, w);
    k_conv<<<dim3(TT / MT, CH / NT, BATCH), 256, SMEM_CONV>>>(out);
}